// round 6
// baseline (speedup 1.0000x reference)
#include <cuda_runtime.h>
#include <cuda_bf16.h>

#define NSRC  200000
#define NDST  100000
#define NEDGE 500000
#define DF    128
#define KTOT  256            // concat feature dim (agg | self)
#define SCAN_BLOCKS 98       // ceil(100000/1024)

// ---------------- static device scratch (no allocations allowed) ----------------
static __device__ __align__(16) float g_A[NDST * KTOT];      // [100k,256] fused A matrix
static __device__ int   g_counts[NDST];
static __device__ int   g_cursor[NDST];
static __device__ int   g_offsets[NDST + 1];
static __device__ int   g_blocksums[SCAN_BLOCKS];
static __device__ int   g_sorted_src[NEDGE];
static __device__ __align__(16) float g_WcT[KTOT * DF];      // WcT[k*128+o] = Wcat[o][k]

// ---------------- kernels ----------------
__global__ void zero_kernel() {
    int i = blockIdx.x * blockDim.x + threadIdx.x;
    if (i < NDST) { g_counts[i] = 0; g_cursor[i] = 0; }
}

__global__ void hist_kernel(const int* __restrict__ dst_idx) {
    int i = blockIdx.x * blockDim.x + threadIdx.x;
    if (i < NEDGE) atomicAdd(&g_counts[dst_idx[i]], 1);
}

__global__ void scan1_kernel() {
    __shared__ int s[1024];
    int t = threadIdx.x;
    int i = blockIdx.x * 1024 + t;
    int v = (i < NDST) ? g_counts[i] : 0;
    s[t] = v;
    __syncthreads();
    for (int off = 1; off < 1024; off <<= 1) {
        int add = (t >= off) ? s[t - off] : 0;
        __syncthreads();
        s[t] += add;
        __syncthreads();
    }
    if (i < NDST) g_offsets[i] = s[t] - v;      // exclusive
    if (t == 1023) g_blocksums[blockIdx.x] = s[1023];
}

__global__ void scan2_kernel() {
    __shared__ int s[SCAN_BLOCKS];
    int t = threadIdx.x;               // 128 threads
    if (t < SCAN_BLOCKS) s[t] = g_blocksums[t];
    __syncthreads();
    if (t == 0) {
        int run = 0;
        for (int b = 0; b < SCAN_BLOCKS; ++b) { int tv = s[b]; s[b] = run; run += tv; }
    }
    __syncthreads();
    if (t < SCAN_BLOCKS) g_blocksums[t] = s[t];
}

__global__ void scan3_kernel() {
    int i = blockIdx.x * blockDim.x + threadIdx.x;
    if (i < NDST) g_offsets[i] += g_blocksums[i >> 10];
    if (i == 0) g_offsets[NDST] = NEDGE;
}

__global__ void scatter_kernel(const int* __restrict__ src_idx,
                               const int* __restrict__ dst_idx) {
    int i = blockIdx.x * blockDim.x + threadIdx.x;
    if (i < NEDGE) {
        int d = dst_idx[i];
        int pos = g_offsets[d] + atomicAdd(&g_cursor[d], 1);
        g_sorted_src[pos] = src_idx[i];
    }
}

__global__ void build_wct_kernel(const float* __restrict__ W1,
                                 const float* __restrict__ W2) {
    int i = blockIdx.x * blockDim.x + threadIdx.x;
    if (i < KTOT * DF) {
        int k = i >> 7, o = i & 127;
        g_WcT[i] = (k < DF) ? W1[o * DF + k] : W2[o * DF + (k - DF)];
    }
}

// one warp per dst row: atomic-free aggregation + self-gather into fused A.
// 2-way unroll: independent accumulators double in-flight gather MLP.
__global__ void agg_kernel(const float* __restrict__ x,
                           const float* __restrict__ degree,
                           const int*  __restrict__ self_ids) {
    int warp = (blockIdx.x * blockDim.x + threadIdx.x) >> 5;
    int lane = threadIdx.x & 31;
    if (warp >= NDST) return;
    int beg = g_offsets[warp];
    int end = g_offsets[warp + 1];
    float4 acc0 = make_float4(0.f, 0.f, 0.f, 0.f);
    float4 acc1 = make_float4(0.f, 0.f, 0.f, 0.f);
    int j = beg;
    for (; j + 1 < end; j += 2) {
        int s0 = __ldg(&g_sorted_src[j]);
        int s1 = __ldg(&g_sorted_src[j + 1]);
        float4 v0 = __ldg(reinterpret_cast<const float4*>(&x[(size_t)s0 * DF + lane * 4]));
        float4 v1 = __ldg(reinterpret_cast<const float4*>(&x[(size_t)s1 * DF + lane * 4]));
        acc0.x += v0.x; acc0.y += v0.y; acc0.z += v0.z; acc0.w += v0.w;
        acc1.x += v1.x; acc1.y += v1.y; acc1.z += v1.z; acc1.w += v1.w;
    }
    if (j < end) {
        int s0 = __ldg(&g_sorted_src[j]);
        float4 v0 = __ldg(reinterpret_cast<const float4*>(&x[(size_t)s0 * DF + lane * 4]));
        acc0.x += v0.x; acc0.y += v0.y; acc0.z += v0.z; acc0.w += v0.w;
    }
    float inv = 1.0f / degree[warp];
    acc0.x = (acc0.x + acc1.x) * inv;
    acc0.y = (acc0.y + acc1.y) * inv;
    acc0.z = (acc0.z + acc1.z) * inv;
    acc0.w = (acc0.w + acc1.w) * inv;
    *reinterpret_cast<float4*>(&g_A[(size_t)warp * KTOT + lane * 4]) = acc0;
    int sid = __ldg(&self_ids[warp]);
    float4 sv = __ldg(reinterpret_cast<const float4*>(&x[(size_t)sid * DF + lane * 4]));
    *reinterpret_cast<float4*>(&g_A[(size_t)warp * KTOT + DF + lane * 4]) = sv;
}

// C[100k,128] = A[100k,256] @ WcT   (register-tiled, 128 rows/block, 512 threads)
#define GEMM_THREADS 512
#define GEMM_ROWS    128
#define AS_STRIDE    68           // 64 + 4 pad (keeps float4 alignment, breaks conflicts)
#define GEMM_SMEM_BYTES ((KTOT * DF + GEMM_ROWS * AS_STRIDE) * 4)

__global__ __launch_bounds__(GEMM_THREADS, 1)
void gemm_kernel(float* __restrict__ out) {
    extern __shared__ float sm[];
    float* Ws = sm;                      // [256][128] k-major
    float* As = sm + KTOT * DF;          // [128][68]  row-major, 64-wide k chunk

    int tid = threadIdx.x;
    for (int i = tid; i < KTOT * DF; i += GEMM_THREADS) Ws[i] = g_WcT[i];

    int row0 = blockIdx.x * GEMM_ROWS;
    int tx = tid & 15;        // 16 col groups -> cols tx*8 .. tx*8+7
    int ty = tid >> 4;        // 32 row groups -> rows ty*4 .. ty*4+3

    float acc[4][8];
#pragma unroll
    for (int i = 0; i < 4; ++i)
#pragma unroll
        for (int j = 0; j < 8; ++j) acc[i][j] = 0.f;

    for (int kc = 0; kc < KTOT; kc += 64) {
        __syncthreads();    // Ws ready (first iter) / As safe to overwrite
#pragma unroll
        for (int it = 0; it < 4; ++it) {
            int lin = it * GEMM_THREADS + tid;       // 2048 float4 loads
            int r = lin >> 4, kq = lin & 15;
            int row = row0 + r; if (row >= NDST) row = NDST - 1;
            float4 v = *reinterpret_cast<const float4*>(&g_A[(size_t)row * KTOT + kc + kq * 4]);
            *reinterpret_cast<float4*>(&As[r * AS_STRIDE + kq * 4]) = v;
        }
        __syncthreads();
#pragma unroll 4
        for (int k = 0; k < 64; ++k) {
            float a0 = As[(ty * 4 + 0) * AS_STRIDE + k];
            float a1 = As[(ty * 4 + 1) * AS_STRIDE + k];
            float a2 = As[(ty * 4 + 2) * AS_STRIDE + k];
            float a3 = As[(ty * 4 + 3) * AS_STRIDE + k];
            const float* wrow = &Ws[(kc + k) * DF + tx * 8];
            float4 w0 = *reinterpret_cast<const float4*>(wrow);
            float4 w1 = *reinterpret_cast<const float4*>(wrow + 4);
            float w[8] = {w0.x, w0.y, w0.z, w0.w, w1.x, w1.y, w1.z, w1.w};
#pragma unroll
            for (int j = 0; j < 8; ++j) {
                acc[0][j] += a0 * w[j];
                acc[1][j] += a1 * w[j];
                acc[2][j] += a2 * w[j];
                acc[3][j] += a3 * w[j];
            }
        }
    }

#pragma unroll
    for (int i = 0; i < 4; ++i) {
        int row = row0 + ty * 4 + i;
        if (row < NDST) {
            float4 o0 = make_float4(acc[i][0], acc[i][1], acc[i][2], acc[i][3]);
            float4 o1 = make_float4(acc[i][4], acc[i][5], acc[i][6], acc[i][7]);
            *reinterpret_cast<float4*>(&out[(size_t)row * DF + tx * 8])     = o0;
            *reinterpret_cast<float4*>(&out[(size_t)row * DF + tx * 8 + 4]) = o1;
        }
    }
}

// ---------------- launch ----------------
extern "C" void kernel_launch(void* const* d_in, const int* in_sizes, int n_in,
                              void* d_out, int out_size) {
    const float* x       = (const float*)d_in[0];
    const float* W1      = (const float*)d_in[1];
    const float* W2      = (const float*)d_in[2];
    const float* degree  = (const float*)d_in[3];
    const int*   src_idx = (const int*)  d_in[4];
    const int*   dst_idx = (const int*)  d_in[5];
    const int*   self_ids= (const int*)  d_in[6];
    float* out = (float*)d_out;

    cudaFuncSetAttribute(gemm_kernel,
                         cudaFuncAttributeMaxDynamicSharedMemorySize,
                         GEMM_SMEM_BYTES);

    zero_kernel   <<<(NDST + 255) / 256, 256>>>();
    hist_kernel   <<<(NEDGE + 255) / 256, 256>>>(dst_idx);
    scan1_kernel  <<<SCAN_BLOCKS, 1024>>>();
    scan2_kernel  <<<1, 128>>>();
    scan3_kernel  <<<(NDST + 255) / 256, 256>>>();
    scatter_kernel<<<(NEDGE + 255) / 256, 256>>>(src_idx, dst_idx);
    build_wct_kernel<<<(KTOT * DF + 255) / 256, 256>>>(W1, W2);
    agg_kernel    <<<(NDST * 32 + 255) / 256, 256>>>(x, degree, self_ids);
    gemm_kernel   <<<(NDST + GEMM_ROWS - 1) / GEMM_ROWS, GEMM_THREADS,
                     GEMM_SMEM_BYTES>>>(out);
}

// round 7
// speedup vs baseline: 2.1537x; 2.1537x over previous
#include <cuda_runtime.h>
#include <cuda_bf16.h>
#include <cstdint>

#define NSRC  200000
#define NDST  100000
#define NEDGE 500000
#define DF    128
#define KTOT  256            // concat feature dim (agg | self)
#define SCAN_BLOCKS 98       // ceil(100000/1024)

// ---------------- static device scratch (no allocations allowed) ----------------
static __device__ __align__(16) __nv_bfloat16 g_Ahi[(size_t)NDST * KTOT]; // 51.2 MB
static __device__ __align__(16) __nv_bfloat16 g_Alo[(size_t)NDST * KTOT]; // 51.2 MB
static __device__ __align__(16) __nv_bfloat16 g_Whi[DF * KTOT];           // [n=128][k=256]
static __device__ __align__(16) __nv_bfloat16 g_Wlo[DF * KTOT];
static __device__ int   g_counts[NDST];
static __device__ int   g_cursor[NDST];
static __device__ int   g_offsets[NDST + 1];
static __device__ int   g_blocksums[SCAN_BLOCKS];
static __device__ int   g_sorted_src[NEDGE];

// ---------------- sort / CSR kernels ----------------
__global__ void zero_kernel() {
    int i = blockIdx.x * blockDim.x + threadIdx.x;
    if (i < NDST) { g_counts[i] = 0; g_cursor[i] = 0; }
}

__global__ void hist_kernel(const int* __restrict__ dst_idx) {
    int i = blockIdx.x * blockDim.x + threadIdx.x;
    if (i < NEDGE) atomicAdd(&g_counts[dst_idx[i]], 1);
}

__global__ void scan1_kernel() {
    __shared__ int s[1024];
    int t = threadIdx.x;
    int i = blockIdx.x * 1024 + t;
    int v = (i < NDST) ? g_counts[i] : 0;
    s[t] = v;
    __syncthreads();
    for (int off = 1; off < 1024; off <<= 1) {
        int add = (t >= off) ? s[t - off] : 0;
        __syncthreads();
        s[t] += add;
        __syncthreads();
    }
    if (i < NDST) g_offsets[i] = s[t] - v;      // exclusive
    if (t == 1023) g_blocksums[blockIdx.x] = s[1023];
}

__global__ void scan2_kernel() {
    __shared__ int s[SCAN_BLOCKS];
    int t = threadIdx.x;               // 128 threads
    if (t < SCAN_BLOCKS) s[t] = g_blocksums[t];
    __syncthreads();
    if (t == 0) {
        int run = 0;
        for (int b = 0; b < SCAN_BLOCKS; ++b) { int tv = s[b]; s[b] = run; run += tv; }
    }
    __syncthreads();
    if (t < SCAN_BLOCKS) g_blocksums[t] = s[t];
}

__global__ void scan3_kernel() {
    int i = blockIdx.x * blockDim.x + threadIdx.x;
    if (i < NDST) g_offsets[i] += g_blocksums[i >> 10];
    if (i == 0) g_offsets[NDST] = NEDGE;
}

__global__ void scatter_kernel(const int* __restrict__ src_idx,
                               const int* __restrict__ dst_idx) {
    int i = blockIdx.x * blockDim.x + threadIdx.x;
    if (i < NEDGE) {
        int d = dst_idx[i];
        int pos = g_offsets[d] + atomicAdd(&g_cursor[d], 1);
        g_sorted_src[pos] = src_idx[i];
    }
}

// W split: g_W{hi,lo}[n*256+k] = split of (k<128 ? W1[n][k] : W2[n][k-128])
__global__ void build_w_kernel(const float* __restrict__ W1,
                               const float* __restrict__ W2) {
    int i = blockIdx.x * blockDim.x + threadIdx.x;
    if (i < DF * KTOT) {
        int n = i >> 8, k = i & 255;
        float v = (k < DF) ? W1[n * DF + k] : W2[n * DF + (k - DF)];
        __nv_bfloat16 h = __float2bfloat16_rn(v);
        __nv_bfloat16 l = __float2bfloat16_rn(v - __bfloat162float(h));
        g_Whi[i] = h;
        g_Wlo[i] = l;
    }
}

// one warp per dst row: atomic-free aggregation + self-gather.
// Emits the fused A row directly as split bf16 (hi + lo).
__device__ __forceinline__ void split_store4(__nv_bfloat16* hi, __nv_bfloat16* lo,
                                             float a0, float a1, float a2, float a3) {
    __nv_bfloat16 h0 = __float2bfloat16_rn(a0);
    __nv_bfloat16 h1 = __float2bfloat16_rn(a1);
    __nv_bfloat16 h2 = __float2bfloat16_rn(a2);
    __nv_bfloat16 h3 = __float2bfloat16_rn(a3);
    __nv_bfloat162* hp = reinterpret_cast<__nv_bfloat162*>(hi);
    hp[0] = __nv_bfloat162(h0, h1);
    hp[1] = __nv_bfloat162(h2, h3);
    __nv_bfloat162* lp = reinterpret_cast<__nv_bfloat162*>(lo);
    lp[0] = __nv_bfloat162(__float2bfloat16_rn(a0 - __bfloat162float(h0)),
                           __float2bfloat16_rn(a1 - __bfloat162float(h1)));
    lp[1] = __nv_bfloat162(__float2bfloat16_rn(a2 - __bfloat162float(h2)),
                           __float2bfloat16_rn(a3 - __bfloat162float(h3)));
}

__global__ void agg_kernel(const float* __restrict__ x,
                           const float* __restrict__ degree,
                           const int*  __restrict__ self_ids) {
    int warp = (blockIdx.x * blockDim.x + threadIdx.x) >> 5;
    int lane = threadIdx.x & 31;
    if (warp >= NDST) return;
    int beg = g_offsets[warp];
    int end = g_offsets[warp + 1];
    float4 acc0 = make_float4(0.f, 0.f, 0.f, 0.f);
    float4 acc1 = make_float4(0.f, 0.f, 0.f, 0.f);
    int j = beg;
    for (; j + 1 < end; j += 2) {
        int s0 = __ldg(&g_sorted_src[j]);
        int s1 = __ldg(&g_sorted_src[j + 1]);
        float4 v0 = __ldg(reinterpret_cast<const float4*>(&x[(size_t)s0 * DF + lane * 4]));
        float4 v1 = __ldg(reinterpret_cast<const float4*>(&x[(size_t)s1 * DF + lane * 4]));
        acc0.x += v0.x; acc0.y += v0.y; acc0.z += v0.z; acc0.w += v0.w;
        acc1.x += v1.x; acc1.y += v1.y; acc1.z += v1.z; acc1.w += v1.w;
    }
    if (j < end) {
        int s0 = __ldg(&g_sorted_src[j]);
        float4 v0 = __ldg(reinterpret_cast<const float4*>(&x[(size_t)s0 * DF + lane * 4]));
        acc0.x += v0.x; acc0.y += v0.y; acc0.z += v0.z; acc0.w += v0.w;
    }
    float inv = 1.0f / degree[warp];
    acc0.x = (acc0.x + acc1.x) * inv;
    acc0.y = (acc0.y + acc1.y) * inv;
    acc0.z = (acc0.z + acc1.z) * inv;
    acc0.w = (acc0.w + acc1.w) * inv;
    size_t base = (size_t)warp * KTOT + lane * 4;
    split_store4(&g_Ahi[base], &g_Alo[base], acc0.x, acc0.y, acc0.z, acc0.w);
    int sid = __ldg(&self_ids[warp]);
    float4 sv = __ldg(reinterpret_cast<const float4*>(&x[(size_t)sid * DF + lane * 4]));
    split_store4(&g_Ahi[base + DF], &g_Alo[base + DF], sv.x, sv.y, sv.z, sv.w);
}

// ---------------- tensor-core GEMM: C[100k,128] = A[100k,256] @ W^T -------------
// split-bf16, 3 mma passes (hi*hi + hi*lo + lo*hi), fp32 accumulate.
#define MT   128             // block m tile
#define KC   64              // k chunk in smem
#define BSTR 72              // smem row stride (bf16): 144B -> conflict-free ldmatrix
#define GEMM_SMEM (4 * MT * BSTR * (int)sizeof(__nv_bfloat16))   // 73728 B

__device__ __forceinline__ uint32_t smaddr(const void* p) {
    return (uint32_t)__cvta_generic_to_shared(p);
}
__device__ __forceinline__ void ldmx4(uint32_t& r0, uint32_t& r1, uint32_t& r2,
                                      uint32_t& r3, uint32_t a) {
    asm volatile("ldmatrix.sync.aligned.m8n8.x4.shared.b16 {%0,%1,%2,%3}, [%4];\n"
                 : "=r"(r0), "=r"(r1), "=r"(r2), "=r"(r3) : "r"(a));
}
__device__ __forceinline__ void mma16816(float* d, const uint32_t* a, const uint32_t* b) {
    asm volatile(
        "mma.sync.aligned.m16n8k16.row.col.f32.bf16.bf16.f32 "
        "{%0,%1,%2,%3}, {%4,%5,%6,%7}, {%8,%9}, {%0,%1,%2,%3};\n"
        : "+f"(d[0]), "+f"(d[1]), "+f"(d[2]), "+f"(d[3])
        : "r"(a[0]), "r"(a[1]), "r"(a[2]), "r"(a[3]), "r"(b[0]), "r"(b[1]));
}

__global__ __launch_bounds__(256, 1)
void gemm_mma_kernel(float* __restrict__ out) {
    extern __shared__ __nv_bfloat16 sm[];
    __nv_bfloat16* Ah = sm;
    __nv_bfloat16* Al = Ah + MT * BSTR;
    __nv_bfloat16* Bh = Al + MT * BSTR;
    __nv_bfloat16* Bl = Bh + MT * BSTR;

    int tid = threadIdx.x;
    int lane = tid & 31;
    int w    = tid >> 5;        // 8 warps: 2 (m) x 4 (n)
    int wm = w >> 2, wn = w & 3;
    int m0 = blockIdx.x * MT;

    float acc[4][4][4];
#pragma unroll
    for (int mi = 0; mi < 4; ++mi)
#pragma unroll
        for (int ni = 0; ni < 4; ++ni)
#pragma unroll
            for (int q = 0; q < 4; ++q) acc[mi][ni][q] = 0.f;

    // per-lane ldmatrix source coordinates
    int arow = wm * 64 + (lane & 7) + ((lane >> 3) & 1) * 8;
    int acolo = ((lane >> 4) & 1) * 8;
    int brow = wn * 32 + (lane & 7) + ((lane >> 4) & 1) * 8;
    int bcolo = ((lane >> 3) & 1) * 8;

    for (int kc = 0; kc < KTOT; kc += KC) {
        __syncthreads();
#pragma unroll
        for (int it = 0; it < 4; ++it) {
            int lin = it * 256 + tid;              // 1024 chunks of 16B per tile
            int r = lin >> 3, c8 = (lin & 7) * 8;
            int grow = m0 + r; if (grow >= NDST) grow = NDST - 1;
            *reinterpret_cast<uint4*>(&Ah[r * BSTR + c8]) =
                *reinterpret_cast<const uint4*>(&g_Ahi[(size_t)grow * KTOT + kc + c8]);
            *reinterpret_cast<uint4*>(&Al[r * BSTR + c8]) =
                *reinterpret_cast<const uint4*>(&g_Alo[(size_t)grow * KTOT + kc + c8]);
            *reinterpret_cast<uint4*>(&Bh[r * BSTR + c8]) =
                *reinterpret_cast<const uint4*>(&g_Whi[r * KTOT + kc + c8]);
            *reinterpret_cast<uint4*>(&Bl[r * BSTR + c8]) =
                *reinterpret_cast<const uint4*>(&g_Wlo[r * KTOT + kc + c8]);
        }
        __syncthreads();

#pragma unroll
        for (int ks = 0; ks < KC; ks += 16) {
            uint32_t ah[4][4], al[4][4], bh[4][2], bl[4][2];
#pragma unroll
            for (int mi = 0; mi < 4; ++mi) {
                ldmx4(ah[mi][0], ah[mi][1], ah[mi][2], ah[mi][3],
                      smaddr(&Ah[(arow + mi * 16) * BSTR + ks + acolo]));
                ldmx4(al[mi][0], al[mi][1], al[mi][2], al[mi][3],
                      smaddr(&Al[(arow + mi * 16) * BSTR + ks + acolo]));
            }
#pragma unroll
            for (int np = 0; np < 2; ++np) {
                uint32_t r0, r1, r2, r3;
                ldmx4(r0, r1, r2, r3,
                      smaddr(&Bh[(brow + np * 16) * BSTR + ks + bcolo]));
                bh[np * 2][0] = r0; bh[np * 2][1] = r1;
                bh[np * 2 + 1][0] = r2; bh[np * 2 + 1][1] = r3;
                ldmx4(r0, r1, r2, r3,
                      smaddr(&Bl[(brow + np * 16) * BSTR + ks + bcolo]));
                bl[np * 2][0] = r0; bl[np * 2][1] = r1;
                bl[np * 2 + 1][0] = r2; bl[np * 2 + 1][1] = r3;
            }
#pragma unroll
            for (int mi = 0; mi < 4; ++mi)
#pragma unroll
                for (int ni = 0; ni < 4; ++ni) {
                    mma16816(acc[mi][ni], ah[mi], bh[ni]);   // hi*hi
                    mma16816(acc[mi][ni], ah[mi], bl[ni]);   // hi*lo
                    mma16816(acc[mi][ni], al[mi], bh[ni]);   // lo*hi
                }
        }
    }

    // epilogue: C fragment -> global
#pragma unroll
    for (int mi = 0; mi < 4; ++mi) {
#pragma unroll
        for (int ni = 0; ni < 4; ++ni) {
            int row = m0 + wm * 64 + mi * 16 + (lane >> 2);
            int col = wn * 32 + ni * 8 + 2 * (lane & 3);
            if (row < NDST) {
                float2 v = make_float2(acc[mi][ni][0], acc[mi][ni][1]);
                *reinterpret_cast<float2*>(&out[(size_t)row * DF + col]) = v;
            }
            if (row + 8 < NDST) {
                float2 v = make_float2(acc[mi][ni][2], acc[mi][ni][3]);
                *reinterpret_cast<float2*>(&out[(size_t)(row + 8) * DF + col]) = v;
            }
        }
    }
}

// ---------------- launch ----------------
extern "C" void kernel_launch(void* const* d_in, const int* in_sizes, int n_in,
                              void* d_out, int out_size) {
    const float* x       = (const float*)d_in[0];
    const float* W1      = (const float*)d_in[1];
    const float* W2      = (const float*)d_in[2];
    const float* degree  = (const float*)d_in[3];
    const int*   src_idx = (const int*)  d_in[4];
    const int*   dst_idx = (const int*)  d_in[5];
    const int*   self_ids= (const int*)  d_in[6];
    float* out = (float*)d_out;

    cudaFuncSetAttribute(gemm_mma_kernel,
                         cudaFuncAttributeMaxDynamicSharedMemorySize, GEMM_SMEM);

    zero_kernel   <<<(NDST + 255) / 256, 256>>>();
    hist_kernel   <<<(NEDGE + 255) / 256, 256>>>(dst_idx);
    scan1_kernel  <<<SCAN_BLOCKS, 1024>>>();
    scan2_kernel  <<<1, 128>>>();
    scan3_kernel  <<<(NDST + 255) / 256, 256>>>();
    scatter_kernel<<<(NEDGE + 255) / 256, 256>>>(src_idx, dst_idx);
    build_w_kernel<<<(DF * KTOT + 255) / 256, 256>>>(W1, W2);
    agg_kernel    <<<(NDST * 32 + 255) / 256, 256>>>(x, degree, self_ids);
    gemm_mma_kernel<<<(NDST + MT - 1) / MT, 256, GEMM_SMEM>>>(out);
}